// round 2
// baseline (speedup 1.0000x reference)
#include <cuda_runtime.h>
#include <math.h>

// ---------------- problem constants (fixed-shape benchmark) ----------------
#define T_TOKENS 4096
#define H_DIM    2048
#define F_DIM    7168
#define N_EXP    8
#define NPAIRS   (T_TOKENS * 2)     // top-2: 8192 (token, expert) pairs
#define BM       128
#define BK       16
#define BN       64
#define MAX_RT   (NPAIRS / BM + N_EXP)   // 72 worst-case row tiles

// ---------------- device scratch (static: no allocations allowed) ----------
__device__ __align__(16) float g_h[(size_t)NPAIRS * F_DIM];   // SwiGLU activations
__device__ __align__(16) float g_y[(size_t)NPAIRS * H_DIM];   // per-pair outputs (weighted)
__device__ int   g_gtoken[NPAIRS];     // grouped-by-expert token index
__device__ float g_gweight[NPAIRS];    // grouped routing weight
__device__ int   g_pairrow[NPAIRS];    // [t*2+k] -> grouped row index
__device__ int   g_sel[NPAIRS];        // [t*2+k] -> expert id
__device__ float g_wt[NPAIRS];         // [t*2+k] -> normalized weight
__device__ int   g_counts[N_EXP];
__device__ int   g_cursor[N_EXP];
__device__ int   g_offsets[N_EXP + 1];
__device__ int   g_tile_e[MAX_RT];
__device__ int   g_tile_r[MAX_RT];
__device__ int   g_ntiles;

// ---------------------------------------------------------------------------
__global__ void init_kernel() {
    if (threadIdx.x < N_EXP) g_counts[threadIdx.x] = 0;
}

// One block per token: logits = x[t] . gate_w[e], softmax-top2 weights.
__global__ void router_kernel(const float* __restrict__ x,
                              const float* __restrict__ gw,
                              float* __restrict__ logits_out) {
    const int t   = blockIdx.x;
    const int tid = threadIdx.x;

    float acc[N_EXP];
#pragma unroll
    for (int e = 0; e < N_EXP; e++) acc[e] = 0.0f;

    const float4* xr = (const float4*)(x + (size_t)t * H_DIM);
#pragma unroll 2
    for (int i = tid; i < H_DIM / 4; i += 256) {
        float4 xv = xr[i];
#pragma unroll
        for (int e = 0; e < N_EXP; e++) {
            float4 gv = ((const float4*)(gw + (size_t)e * H_DIM))[i];
            acc[e] += xv.x * gv.x + xv.y * gv.y + xv.z * gv.z + xv.w * gv.w;
        }
    }
    // warp reduce
#pragma unroll
    for (int e = 0; e < N_EXP; e++)
#pragma unroll
        for (int off = 16; off > 0; off >>= 1)
            acc[e] += __shfl_down_sync(0xffffffffu, acc[e], off);

    __shared__ float sred[N_EXP][8];
    __shared__ float slog[N_EXP];
    const int w = tid >> 5, lane = tid & 31;
    if (lane == 0) {
#pragma unroll
        for (int e = 0; e < N_EXP; e++) sred[e][w] = acc[e];
    }
    __syncthreads();
    if (tid < N_EXP) {
        float s = 0.0f;
#pragma unroll
        for (int ww = 0; ww < 8; ww++) s += sred[tid][ww];
        slog[tid] = s;
        if (logits_out) logits_out[(size_t)t * N_EXP + tid] = s;
    }
    __syncthreads();
    if (tid == 0) {
        int i0 = 0; float v0 = slog[0];
#pragma unroll
        for (int e = 1; e < N_EXP; e++) { if (slog[e] > v0) { v0 = slog[e]; i0 = e; } }
        int i1 = -1; float v1 = -1e30f;
#pragma unroll
        for (int e = 0; e < N_EXP; e++) {
            if (e == i0) continue;
            if (slog[e] > v1) { v1 = slog[e]; i1 = e; }
        }
        // normalized top-2 softmax weights: w0 = p0/(p0+p1)
        float w0 = 1.0f / (1.0f + expf(v1 - v0));
        float w1 = 1.0f - w0;
        g_sel[2 * t]     = i0;  g_sel[2 * t + 1] = i1;
        g_wt[2 * t]      = w0;  g_wt[2 * t + 1]  = w1;
        atomicAdd(&g_counts[i0], 1);
        atomicAdd(&g_counts[i1], 1);
    }
}

// Single thread: offsets + row-tile table (tiny: 8 experts, <=72 tiles).
__global__ void scan_kernel() {
    int off = 0, nt = 0;
    for (int e = 0; e < N_EXP; e++) {
        g_offsets[e] = off;
        g_cursor[e]  = off;
        int c = g_counts[e];
        int ntile = (c + BM - 1) / BM;
        for (int i = 0; i < ntile; i++) { g_tile_e[nt] = e; g_tile_r[nt] = i * BM; nt++; }
        off += c;
    }
    g_offsets[N_EXP] = off;
    g_ntiles = nt;
}

__global__ void scatter_kernel() {
    int t = blockIdx.x * blockDim.x + threadIdx.x;
    if (t >= T_TOKENS) return;
#pragma unroll
    for (int k = 0; k < 2; k++) {
        int e   = g_sel[2 * t + k];
        int idx = atomicAdd(&g_cursor[e], 1);
        g_gtoken[idx]      = t;
        g_gweight[idx]     = g_wt[2 * t + k];
        g_pairrow[2 * t + k] = idx;
    }
}

// ---------------- GEMM1: h = silu(X w1^T) * (X w3^T), grouped by expert -----
__global__ void __launch_bounds__(256)
gemm1_kernel(const float* __restrict__ x,
             const float* __restrict__ w1,
             const float* __restrict__ w3) {
    const int rt = blockIdx.y;
    if (rt >= g_ntiles) return;
    const int e        = g_tile_e[rt];
    const int row_base = g_offsets[e] + g_tile_r[rt];
    const int n_valid  = g_offsets[e + 1] - row_base;
    const int f0       = blockIdx.x * BN;
    const int tid      = threadIdx.x;

    __shared__ __align__(16) float As [BK][BM];
    __shared__ __align__(16) float Bs1[BK][BN];
    __shared__ __align__(16) float Bs3[BK][BN];

    const int la_r = tid >> 2;          // 0..63
    const int la_k = (tid & 3) * 4;     // 0,4,8,12
    const int r0c  = min(row_base + la_r,      NPAIRS - 1);
    const int r1c  = min(row_base + la_r + 64, NPAIRS - 1);
    const float* a0p = x  + (size_t)g_gtoken[r0c] * H_DIM + la_k;
    const float* a1p = x  + (size_t)g_gtoken[r1c] * H_DIM + la_k;
    const float* b1p = w1 + ((size_t)e * F_DIM + f0 + la_r) * H_DIM + la_k;
    const float* b3p = w3 + ((size_t)e * F_DIM + f0 + la_r) * H_DIM + la_k;

    const int ty = tid >> 4, tx = tid & 15;

    float acc1[8][4], acc3[8][4];
#pragma unroll
    for (int i = 0; i < 8; i++)
#pragma unroll
        for (int j = 0; j < 4; j++) { acc1[i][j] = 0.0f; acc3[i][j] = 0.0f; }

    for (int k0 = 0; k0 < H_DIM; k0 += BK) {
        float4 av0 = *(const float4*)(a0p + k0);
        float4 av1 = *(const float4*)(a1p + k0);
        float4 bv1 = *(const float4*)(b1p + k0);
        float4 bv3 = *(const float4*)(b3p + k0);
        __syncthreads();
        As[la_k + 0][la_r] = av0.x; As[la_k + 1][la_r] = av0.y;
        As[la_k + 2][la_r] = av0.z; As[la_k + 3][la_r] = av0.w;
        As[la_k + 0][la_r + 64] = av1.x; As[la_k + 1][la_r + 64] = av1.y;
        As[la_k + 2][la_r + 64] = av1.z; As[la_k + 3][la_r + 64] = av1.w;
        Bs1[la_k + 0][la_r] = bv1.x; Bs1[la_k + 1][la_r] = bv1.y;
        Bs1[la_k + 2][la_r] = bv1.z; Bs1[la_k + 3][la_r] = bv1.w;
        Bs3[la_k + 0][la_r] = bv3.x; Bs3[la_k + 1][la_r] = bv3.y;
        Bs3[la_k + 2][la_r] = bv3.z; Bs3[la_k + 3][la_r] = bv3.w;
        __syncthreads();
#pragma unroll
        for (int k = 0; k < BK; k++) {
            float4 a04 = *(const float4*)&As[k][ty * 8];
            float4 a14 = *(const float4*)&As[k][ty * 8 + 4];
            float4 b1v = *(const float4*)&Bs1[k][tx * 4];
            float4 b3v = *(const float4*)&Bs3[k][tx * 4];
            float a[8] = {a04.x, a04.y, a04.z, a04.w, a14.x, a14.y, a14.z, a14.w};
            float b1a[4] = {b1v.x, b1v.y, b1v.z, b1v.w};
            float b3a[4] = {b3v.x, b3v.y, b3v.z, b3v.w};
#pragma unroll
            for (int i = 0; i < 8; i++)
#pragma unroll
                for (int j = 0; j < 4; j++) {
                    acc1[i][j] += a[i] * b1a[j];
                    acc3[i][j] += a[i] * b3a[j];
                }
        }
    }
#pragma unroll
    for (int i = 0; i < 8; i++) {
        int r = ty * 8 + i;
        if (r < n_valid) {
            float4 hv;
            float s;
            s = acc1[i][0]; hv.x = s * (1.0f / (1.0f + expf(-s))) * acc3[i][0];
            s = acc1[i][1]; hv.y = s * (1.0f / (1.0f + expf(-s))) * acc3[i][1];
            s = acc1[i][2]; hv.z = s * (1.0f / (1.0f + expf(-s))) * acc3[i][2];
            s = acc1[i][3]; hv.w = s * (1.0f / (1.0f + expf(-s))) * acc3[i][3];
            *(float4*)&g_h[(size_t)(row_base + r) * F_DIM + f0 + tx * 4] = hv;
        }
    }
}

// ---------------- GEMM2: y = (h w2^T) * route_weight -----------------------
__global__ void __launch_bounds__(256)
gemm2_kernel(const float* __restrict__ w2) {
    const int rt = blockIdx.y;
    if (rt >= g_ntiles) return;
    const int e        = g_tile_e[rt];
    const int row_base = g_offsets[e] + g_tile_r[rt];
    const int n_valid  = g_offsets[e + 1] - row_base;
    const int h0       = blockIdx.x * BN;
    const int tid      = threadIdx.x;

    __shared__ __align__(16) float As[BK][BM];
    __shared__ __align__(16) float Bs[BK][BN];

    const int la_r = tid >> 2;
    const int la_k = (tid & 3) * 4;
    const int r0c  = min(row_base + la_r,      NPAIRS - 1);
    const int r1c  = min(row_base + la_r + 64, NPAIRS - 1);
    const float* a0p = g_h + (size_t)r0c * F_DIM + la_k;
    const float* a1p = g_h + (size_t)r1c * F_DIM + la_k;
    const float* bp  = w2  + ((size_t)e * H_DIM + h0 + la_r) * F_DIM + la_k;

    const int ty = tid >> 4, tx = tid & 15;

    float acc[8][4];
#pragma unroll
    for (int i = 0; i < 8; i++)
#pragma unroll
        for (int j = 0; j < 4; j++) acc[i][j] = 0.0f;

    for (int k0 = 0; k0 < F_DIM; k0 += BK) {
        float4 av0 = *(const float4*)(a0p + k0);
        float4 av1 = *(const float4*)(a1p + k0);
        float4 bv  = *(const float4*)(bp + k0);
        __syncthreads();
        As[la_k + 0][la_r] = av0.x; As[la_k + 1][la_r] = av0.y;
        As[la_k + 2][la_r] = av0.z; As[la_k + 3][la_r] = av0.w;
        As[la_k + 0][la_r + 64] = av1.x; As[la_k + 1][la_r + 64] = av1.y;
        As[la_k + 2][la_r + 64] = av1.z; As[la_k + 3][la_r + 64] = av1.w;
        Bs[la_k + 0][la_r] = bv.x; Bs[la_k + 1][la_r] = bv.y;
        Bs[la_k + 2][la_r] = bv.z; Bs[la_k + 3][la_r] = bv.w;
        __syncthreads();
#pragma unroll
        for (int k = 0; k < BK; k++) {
            float4 a04 = *(const float4*)&As[k][ty * 8];
            float4 a14 = *(const float4*)&As[k][ty * 8 + 4];
            float4 bv4 = *(const float4*)&Bs[k][tx * 4];
            float a[8] = {a04.x, a04.y, a04.z, a04.w, a14.x, a14.y, a14.z, a14.w};
            float b[4] = {bv4.x, bv4.y, bv4.z, bv4.w};
#pragma unroll
            for (int i = 0; i < 8; i++)
#pragma unroll
                for (int j = 0; j < 4; j++) acc[i][j] += a[i] * b[j];
        }
    }
#pragma unroll
    for (int i = 0; i < 8; i++) {
        int r = ty * 8 + i;
        if (r < n_valid) {
            float wgt = g_gweight[row_base + r];
            float4 yv;
            yv.x = acc[i][0] * wgt; yv.y = acc[i][1] * wgt;
            yv.z = acc[i][2] * wgt; yv.w = acc[i][3] * wgt;
            *(float4*)&g_y[(size_t)(row_base + r) * H_DIM + h0 + tx * 4] = yv;
        }
    }
}

// ---------------- combine: out[t] = y[slot(t,0)] + y[slot(t,1)] ------------
__global__ void combine_kernel(float* __restrict__ out) {
    int idx = blockIdx.x * blockDim.x + threadIdx.x;     // over T*H/4
    int t = idx / (H_DIM / 4);
    int c = idx % (H_DIM / 4);
    int p0 = g_pairrow[2 * t];
    int p1 = g_pairrow[2 * t + 1];
    float4 y0 = *(const float4*)&g_y[(size_t)p0 * H_DIM + c * 4];
    float4 y1 = *(const float4*)&g_y[(size_t)p1 * H_DIM + c * 4];
    float4 o;
    o.x = y0.x + y1.x; o.y = y0.y + y1.y;
    o.z = y0.z + y1.z; o.w = y0.w + y1.w;
    ((float4*)out)[idx] = o;
}

// ---------------------------------------------------------------------------
extern "C" void kernel_launch(void* const* d_in, const int* in_sizes, int n_in,
                              void* d_out, int out_size) {
    const float* x  = (const float*)d_in[0];   // hidden_states [B,S,H]
    const float* gw = (const float*)d_in[1];   // gate_w [E,H]
    const float* w1 = (const float*)d_in[2];   // w1 [E,F,H]
    const float* w2 = (const float*)d_in[3];   // w2 [E,H,F]
    const float* w3 = (const float*)d_in[4];   // w3 [E,F,H]
    float* out = (float*)d_out;
    // output = flatten(out) ++ flatten(router_logits) if room
    float* logits = nullptr;
    if (out_size >= T_TOKENS * H_DIM + T_TOKENS * N_EXP)
        logits = out + (size_t)T_TOKENS * H_DIM;

    init_kernel<<<1, 32>>>();
    router_kernel<<<T_TOKENS, 256>>>(x, gw, logits);
    scan_kernel<<<1, 1>>>();
    scatter_kernel<<<(T_TOKENS + 255) / 256, 256>>>();

    dim3 g1(F_DIM / BN, MAX_RT);
    gemm1_kernel<<<g1, 256>>>(x, w1, w3);
    dim3 g2(H_DIM / BN, MAX_RT);
    gemm2_kernel<<<g2, 256>>>(w2);

    combine_kernel<<<(T_TOKENS * (H_DIM / 4)) / 256, 256>>>(out);
}

// round 8
// speedup vs baseline: 2.0353x; 2.0353x over previous
#include <cuda_runtime.h>
#include <cstdint>
#include <math.h>

#define T_TOKENS 4096
#define H_DIM    2048
#define F_DIM    7168
#define N_EXP    8
#define NPAIRS   (T_TOKENS * 2)
#define BM       128
#define BK       32
#define MAX_RT   (NPAIRS / BM + N_EXP)   // 72

// row stride in smem (bytes): 32 bf16 = 64B data + 16B pad (conflict-free frags)
#define SROW     80
#define STAGE_B  (4 * BM * SROW)          // A_hi A_lo B_hi B_lo per stage = 40960
#define G_SMEM   (2 * STAGE_B)            // 81920

__device__ __align__(16) unsigned short g_h_hi[(size_t)NPAIRS * F_DIM];
__device__ __align__(16) unsigned short g_h_lo[(size_t)NPAIRS * F_DIM];
__device__ __align__(16) float g_y[(size_t)NPAIRS * H_DIM];
__device__ int   g_gtoken[NPAIRS];
__device__ float g_gweight[NPAIRS];
__device__ int   g_pairrow[NPAIRS];
__device__ int   g_sel[NPAIRS];
__device__ float g_wt[NPAIRS];
__device__ int   g_counts[N_EXP];
__device__ int   g_cursor[N_EXP];
__device__ int   g_offsets[N_EXP + 1];
__device__ int   g_tile_e[MAX_RT];
__device__ int   g_tile_r[MAX_RT];
__device__ int   g_ntiles;

// ---------------- helpers ----------------
__device__ __forceinline__ uint32_t pkbf2(float lo, float hi) {
    uint32_t r;
    asm("cvt.rn.bf16x2.f32 %0, %1, %2;" : "=r"(r) : "f"(hi), "f"(lo));
    return r;   // low 16 bits = bf16(lo), high = bf16(hi)
}
// split float4 -> hi pair + lo pair u32s
__device__ __forceinline__ void split4(float4 v, uint32_t& h0, uint32_t& h1,
                                       uint32_t& l0, uint32_t& l1) {
    h0 = pkbf2(v.x, v.y);
    h1 = pkbf2(v.z, v.w);
    float r0 = v.x - __uint_as_float(h0 << 16);
    float r1 = v.y - __uint_as_float(h0 & 0xffff0000u);
    float r2 = v.z - __uint_as_float(h1 << 16);
    float r3 = v.w - __uint_as_float(h1 & 0xffff0000u);
    l0 = pkbf2(r0, r1);
    l1 = pkbf2(r2, r3);
}
__device__ __forceinline__ void mma_bf16(float* d, const uint32_t* a, const uint32_t* b) {
    asm volatile(
        "mma.sync.aligned.m16n8k16.row.col.f32.bf16.bf16.f32 "
        "{%0,%1,%2,%3}, {%4,%5,%6,%7}, {%8,%9}, {%0,%1,%2,%3};"
        : "+f"(d[0]), "+f"(d[1]), "+f"(d[2]), "+f"(d[3])
        : "r"(a[0]), "r"(a[1]), "r"(a[2]), "r"(a[3]), "r"(b[0]), "r"(b[1]));
}

// ---------------- routing ----------------
__global__ void init_kernel() {
    if (threadIdx.x < N_EXP) g_counts[threadIdx.x] = 0;
}

__global__ void router_kernel(const float* __restrict__ x, const float* __restrict__ gw,
                              float* __restrict__ logits_out) {
    const int t = blockIdx.x, tid = threadIdx.x;
    float acc[N_EXP];
#pragma unroll
    for (int e = 0; e < N_EXP; e++) acc[e] = 0.0f;
    const float4* xr = (const float4*)(x + (size_t)t * H_DIM);
    for (int i = tid; i < H_DIM / 4; i += 256) {
        float4 xv = xr[i];
#pragma unroll
        for (int e = 0; e < N_EXP; e++) {
            float4 gv = ((const float4*)(gw + (size_t)e * H_DIM))[i];
            acc[e] += xv.x * gv.x + xv.y * gv.y + xv.z * gv.z + xv.w * gv.w;
        }
    }
#pragma unroll
    for (int e = 0; e < N_EXP; e++)
#pragma unroll
        for (int off = 16; off > 0; off >>= 1)
            acc[e] += __shfl_down_sync(0xffffffffu, acc[e], off);
    __shared__ float sred[N_EXP][8];
    __shared__ float slog[N_EXP];
    const int w = tid >> 5, lane = tid & 31;
    if (lane == 0)
#pragma unroll
        for (int e = 0; e < N_EXP; e++) sred[e][w] = acc[e];
    __syncthreads();
    if (tid < N_EXP) {
        float s = 0.0f;
#pragma unroll
        for (int ww = 0; ww < 8; ww++) s += sred[tid][ww];
        slog[tid] = s;
        if (logits_out) logits_out[(size_t)t * N_EXP + tid] = s;
    }
    __syncthreads();
    if (tid == 0) {
        int i0 = 0; float v0 = slog[0];
#pragma unroll
        for (int e = 1; e < N_EXP; e++) if (slog[e] > v0) { v0 = slog[e]; i0 = e; }
        int i1 = -1; float v1 = -1e30f;
#pragma unroll
        for (int e = 0; e < N_EXP; e++) {
            if (e == i0) continue;
            if (slog[e] > v1) { v1 = slog[e]; i1 = e; }
        }
        float w0 = 1.0f / (1.0f + expf(v1 - v0));
        g_sel[2 * t] = i0; g_sel[2 * t + 1] = i1;
        g_wt[2 * t] = w0;  g_wt[2 * t + 1] = 1.0f - w0;
        atomicAdd(&g_counts[i0], 1);
        atomicAdd(&g_counts[i1], 1);
    }
}

__global__ void scan_kernel() {
    int off = 0, nt = 0;
    for (int e = 0; e < N_EXP; e++) {
        g_offsets[e] = off; g_cursor[e] = off;
        int c = g_counts[e];
        for (int i = 0; i < (c + BM - 1) / BM; i++) { g_tile_e[nt] = e; g_tile_r[nt] = i * BM; nt++; }
        off += c;
    }
    g_offsets[N_EXP] = off;
    g_ntiles = nt;
}

__global__ void scatter_kernel() {
    int t = blockIdx.x * blockDim.x + threadIdx.x;
    if (t >= T_TOKENS) return;
#pragma unroll
    for (int k = 0; k < 2; k++) {
        int e = g_sel[2 * t + k];
        int idx = atomicAdd(&g_cursor[e], 1);
        g_gtoken[idx] = t;
        g_gweight[idx] = g_wt[2 * t + k];
        g_pairrow[2 * t + k] = idx;
    }
}

// ======================= GEMM1 (mma.sync bf16-split) =======================
// CTA: 128 rows x (64 w1-cols + 64 w3-cols). 256 thr, 8 warps (4m x 2n),
// warp tile 32x64. BK=32, smem double-buffered.
__global__ void __launch_bounds__(256)
gemm1_mma(const float* __restrict__ x, const float* __restrict__ w1,
          const float* __restrict__ w3) {
    const int rt = blockIdx.y;
    if (rt >= g_ntiles) return;
    const int e = g_tile_e[rt];
    const int row_base = g_offsets[e] + g_tile_r[rt];
    const int n_valid  = g_offsets[e + 1] - row_base;
    const int f0 = blockIdx.x * 64;
    const int t  = threadIdx.x;
    const int wid = t >> 5, lane = t & 31;
    const int wm = wid & 3, wn = wid >> 2;
    const int g = lane >> 2, cc = lane & 3;

    extern __shared__ __align__(16) char smem[];

    // producer mapping: row = t>>1 (0..127), half = t&1 (16 floats each)
    const int prow = t >> 1, phalf = t & 1;
    const float* aptr = x + (size_t)g_gtoken[min(row_base + prow, NPAIRS - 1)] * H_DIM
                        + phalf * 16;
    const float* bptr = (prow < 64)
        ? (w1 + ((size_t)e * F_DIM + f0 + prow) * H_DIM + phalf * 16)
        : (w3 + ((size_t)e * F_DIM + f0 + (prow - 64)) * H_DIM + phalf * 16);

    float4 abuf[4], bbuf[4];
#pragma unroll
    for (int q = 0; q < 4; q++) {
        abuf[q] = ((const float4*)aptr)[q];
        bbuf[q] = ((const float4*)bptr)[q];
    }

    // STS of staged regs into stage s
    auto sts = [&](int s) {
        char* base = smem + s * STAGE_B;
        uint32_t off = (uint32_t)prow * SROW + (phalf * 16) * 2;   // bytes
#pragma unroll
        for (int q = 0; q < 4; q++) {
            uint32_t h0, h1, l0, l1;
            split4(abuf[q], h0, h1, l0, l1);
            *(uint2*)(base + off + q * 8)                 = make_uint2(h0, h1);
            *(uint2*)(base + BM * SROW + off + q * 8)     = make_uint2(l0, l1);
            split4(bbuf[q], h0, h1, l0, l1);
            *(uint2*)(base + 2 * BM * SROW + off + q * 8) = make_uint2(h0, h1);
            *(uint2*)(base + 3 * BM * SROW + off + q * 8) = make_uint2(l0, l1);
        }
    };

    float acc[2][8][4];
#pragma unroll
    for (int mt = 0; mt < 2; mt++)
#pragma unroll
        for (int nt = 0; nt < 8; nt++)
#pragma unroll
            for (int i = 0; i < 4; i++) acc[mt][nt][i] = 0.0f;

    sts(0);
    __syncthreads();

    const int NC = H_DIM / BK;
    for (int c = 0; c < NC; c++) {
        if (c + 1 < NC) {
#pragma unroll
            for (int q = 0; q < 4; q++) {
                abuf[q] = ((const float4*)(aptr + (c + 1) * BK))[q];
                bbuf[q] = ((const float4*)(bptr + (c + 1) * BK))[q];
            }
        }
        const char* base = smem + (c & 1) * STAGE_B;
        const char* Ah = base, *Al = base + BM * SROW;
        const char* Bh = base + 2 * BM * SROW, *Bl = base + 3 * BM * SROW;
#pragma unroll
        for (int ks = 0; ks < 2; ks++) {
            uint32_t bh[8][2], bl[8][2];
#pragma unroll
            for (int nt = 0; nt < 8; nt++) {
                uint32_t bo = (uint32_t)(wn * 64 + nt * 8 + g) * SROW + ks * 32 + cc * 4;
                bh[nt][0] = *(const uint32_t*)(Bh + bo);
                bh[nt][1] = *(const uint32_t*)(Bh + bo + 16);
                bl[nt][0] = *(const uint32_t*)(Bl + bo);
                bl[nt][1] = *(const uint32_t*)(Bl + bo + 16);
            }
#pragma unroll
            for (int mt = 0; mt < 2; mt++) {
                uint32_t ah[4], al[4];
                uint32_t ao = (uint32_t)(wm * 32 + mt * 16 + g) * SROW + ks * 32 + cc * 4;
                ah[0] = *(const uint32_t*)(Ah + ao);
                ah[1] = *(const uint32_t*)(Ah + ao + 8 * SROW);
                ah[2] = *(const uint32_t*)(Ah + ao + 16);
                ah[3] = *(const uint32_t*)(Ah + ao + 8 * SROW + 16);
                al[0] = *(const uint32_t*)(Al + ao);
                al[1] = *(const uint32_t*)(Al + ao + 8 * SROW);
                al[2] = *(const uint32_t*)(Al + ao + 16);
                al[3] = *(const uint32_t*)(Al + ao + 8 * SROW + 16);
#pragma unroll
                for (int nt = 0; nt < 8; nt++) {
                    mma_bf16(acc[mt][nt], ah, bh[nt]);
                    mma_bf16(acc[mt][nt], ah, bl[nt]);
                    mma_bf16(acc[mt][nt], al, bh[nt]);
                }
            }
        }
        if (c + 1 < NC) sts((c + 1) & 1);
        __syncthreads();
    }

    // ---- epilogue: exchange h3 via smem, SwiGLU, split to bf16 hi/lo ----
    float* h3buf = (float*)smem;   // [128][68]
    if (wn == 1) {
#pragma unroll
        for (int mt = 0; mt < 2; mt++)
#pragma unroll
            for (int nt = 0; nt < 8; nt++) {
                int m0 = wm * 32 + mt * 16 + g;
                int f  = nt * 8 + 2 * cc;
                *(float2*)&h3buf[(m0)     * 68 + f] = make_float2(acc[mt][nt][0], acc[mt][nt][1]);
                *(float2*)&h3buf[(m0 + 8) * 68 + f] = make_float2(acc[mt][nt][2], acc[mt][nt][3]);
            }
    }
    __syncthreads();
    if (wn == 0) {
#pragma unroll
        for (int mt = 0; mt < 2; mt++)
#pragma unroll
            for (int nt = 0; nt < 8; nt++) {
#pragma unroll
                for (int hf = 0; hf < 2; hf++) {
                    int m = wm * 32 + mt * 16 + g + hf * 8;
                    if (m >= n_valid) continue;
                    int f = nt * 8 + 2 * cc;
                    float s1a = acc[mt][nt][hf * 2], s1b = acc[mt][nt][hf * 2 + 1];
                    float2 h3 = *(const float2*)&h3buf[m * 68 + f];
                    float ha = s1a / (1.0f + __expf(-s1a)) * h3.x;
                    float hb = s1b / (1.0f + __expf(-s1b)) * h3.y;
                    uint32_t hh = pkbf2(ha, hb);
                    uint32_t ll = pkbf2(ha - __uint_as_float(hh << 16),
                                        hb - __uint_as_float(hh & 0xffff0000u));
                    size_t go = (size_t)(row_base + m) * F_DIM + f0 + f;
                    *(uint32_t*)(g_h_hi + go) = hh;
                    *(uint32_t*)(g_h_lo + go) = ll;
                }
            }
    }
}

// ======================= GEMM2 (mma.sync bf16-split) =======================
// CTA: 128 rows x 128 h-cols. A already split in g_h_hi/lo.
__global__ void __launch_bounds__(256)
gemm2_mma(const float* __restrict__ w2) {
    const int rt = blockIdx.y;
    if (rt >= g_ntiles) return;
    const int e = g_tile_e[rt];
    const int row_base = g_offsets[e] + g_tile_r[rt];
    const int n_valid  = g_offsets[e + 1] - row_base;
    const int h0 = blockIdx.x * 128;
    const int t  = threadIdx.x;
    const int wid = t >> 5, lane = t & 31;
    const int wm = wid & 3, wn = wid >> 2;
    const int g = lane >> 2, cc = lane & 3;

    extern __shared__ __align__(16) char smem[];

    const int prow = t >> 1, phalf = t & 1;
    const int arow = min(row_base + prow, NPAIRS - 1);
    const unsigned short* ahp = g_h_hi + (size_t)arow * F_DIM + phalf * 16;
    const unsigned short* alp = g_h_lo + (size_t)arow * F_DIM + phalf * 16;
    const float* bptr = w2 + ((size_t)e * H_DIM + h0 + prow) * F_DIM + phalf * 16;

    uint4 ahb[2], alb[2];
    float4 bbuf[4];
#pragma unroll
    for (int q = 0; q < 2; q++) {
        ahb[q] = ((const uint4*)ahp)[q];
        alb[q] = ((const uint4*)alp)[q];
    }
#pragma unroll
    for (int q = 0; q < 4; q++) bbuf[q] = ((const float4*)bptr)[q];

    auto sts = [&](int s) {
        char* base = smem + s * STAGE_B;
        uint32_t off = (uint32_t)prow * SROW + (phalf * 16) * 2;
#pragma unroll
        for (int q = 0; q < 2; q++) {
            *(uint4*)(base + off + q * 16)            = ahb[q];
            *(uint4*)(base + BM * SROW + off + q * 16) = alb[q];
        }
#pragma unroll
        for (int q = 0; q < 4; q++) {
            uint32_t h0v, h1v, l0v, l1v;
            split4(bbuf[q], h0v, h1v, l0v, l1v);
            *(uint2*)(base + 2 * BM * SROW + off + q * 8) = make_uint2(h0v, h1v);
            *(uint2*)(base + 3 * BM * SROW + off + q * 8) = make_uint2(l0v, l1v);
        }
    };

    float acc[2][8][4];
#pragma unroll
    for (int mt = 0; mt < 2; mt++)
#pragma unroll
        for (int nt = 0; nt < 8; nt++)
#pragma unroll
            for (int i = 0; i < 4; i++) acc[mt][nt][i] = 0.0f;

    sts(0);
    __syncthreads();

    const int NC = F_DIM / BK;
    for (int c = 0; c < NC; c++) {
        if (c + 1 < NC) {
#pragma unroll
            for (int q = 0; q < 2; q++) {
                ahb[q] = ((const uint4*)(ahp + (c + 1) * BK))[q];
                alb[q] = ((const uint4*)(alp + (c + 1) * BK))[q];
            }
#pragma unroll
            for (int q = 0; q < 4; q++)
                bbuf[q] = ((const float4*)(bptr + (c + 1) * BK))[q];
        }
        const char* base = smem + (c & 1) * STAGE_B;
        const char* Ah = base, *Al = base + BM * SROW;
        const char* Bh = base + 2 * BM * SROW, *Bl = base + 3 * BM * SROW;
#pragma unroll
        for (int ks = 0; ks < 2; ks++) {
            uint32_t bh[8][2], bl[8][2];
#pragma unroll
            for (int nt = 0; nt < 8; nt++) {
                uint32_t bo = (uint32_t)(wn * 64 + nt * 8 + g) * SROW + ks * 32 + cc * 4;
                bh[nt][0] = *(const uint32_t*)(Bh + bo);
                bh[nt][1] = *(const uint32_t*)(Bh + bo + 16);
                bl[nt][0] = *(const uint32_t*)(Bl + bo);
                bl[nt][1] = *(const uint32_t*)(Bl + bo + 16);
            }
#pragma unroll
            for (int mt = 0; mt < 2; mt++) {
                uint32_t ah[4], al[4];
                uint32_t ao = (uint32_t)(wm * 32 + mt * 16 + g) * SROW + ks * 32 + cc * 4;
                ah[0] = *(const uint32_t*)(Ah + ao);
                ah[1] = *(const uint32_t*)(Ah + ao + 8 * SROW);
                ah[2] = *(const uint32_t*)(Ah + ao + 16);
                ah[3] = *(const uint32_t*)(Ah + ao + 8 * SROW + 16);
                al[0] = *(const uint32_t*)(Al + ao);
                al[1] = *(const uint32_t*)(Al + ao + 8 * SROW);
                al[2] = *(const uint32_t*)(Al + ao + 16);
                al[3] = *(const uint32_t*)(Al + ao + 8 * SROW + 16);
#pragma unroll
                for (int nt = 0; nt < 8; nt++) {
                    mma_bf16(acc[mt][nt], ah, bh[nt]);
                    mma_bf16(acc[mt][nt], ah, bl[nt]);
                    mma_bf16(acc[mt][nt], al, bh[nt]);
                }
            }
        }
        if (c + 1 < NC) sts((c + 1) & 1);
        __syncthreads();
    }

    // ---- epilogue: scale by routing weight, write fp32 y ----
#pragma unroll
    for (int mt = 0; mt < 2; mt++) {
#pragma unroll
        for (int hf = 0; hf < 2; hf++) {
            int m = wm * 32 + mt * 16 + g + hf * 8;
            if (m >= n_valid) continue;
            float wgt = g_gweight[row_base + m];
            float* yrow = g_y + (size_t)(row_base + m) * H_DIM + h0 + wn * 64;
#pragma unroll
            for (int nt = 0; nt < 8; nt++) {
                float2 v = make_float2(acc[mt][nt][hf * 2] * wgt,
                                       acc[mt][nt][hf * 2 + 1] * wgt);
                *(float2*)&yrow[nt * 8 + 2 * cc] = v;
            }
        }
    }
}

// ---------------- combine ----------------
__global__ void combine_kernel(float* __restrict__ out) {
    int idx = blockIdx.x * blockDim.x + threadIdx.x;
    int t = idx / (H_DIM / 4), c = idx % (H_DIM / 4);
    int p0 = g_pairrow[2 * t], p1 = g_pairrow[2 * t + 1];
    float4 y0 = *(const float4*)&g_y[(size_t)p0 * H_DIM + c * 4];
    float4 y1 = *(const float4*)&g_y[(size_t)p1 * H_DIM + c * 4];
    ((float4*)out)[idx] = make_float4(y0.x + y1.x, y0.y + y1.y, y0.z + y1.z, y0.w + y1.w);
}

// ---------------------------------------------------------------------------
extern "C" void kernel_launch(void* const* d_in, const int* in_sizes, int n_in,
                              void* d_out, int out_size) {
    const float* x  = (const float*)d_in[0];
    const float* gw = (const float*)d_in[1];
    const float* w1 = (const float*)d_in[2];
    const float* w2 = (const float*)d_in[3];
    const float* w3 = (const float*)d_in[4];
    float* out = (float*)d_out;
    float* logits = nullptr;
    if (out_size >= T_TOKENS * H_DIM + T_TOKENS * N_EXP)
        logits = out + (size_t)T_TOKENS * H_DIM;

    static int attr_done = 0;
    if (!attr_done) {
        cudaFuncSetAttribute(gemm1_mma, cudaFuncAttributeMaxDynamicSharedMemorySize, G_SMEM);
        cudaFuncSetAttribute(gemm2_mma, cudaFuncAttributeMaxDynamicSharedMemorySize, G_SMEM);
        attr_done = 1;
    }

    init_kernel<<<1, 32>>>();
    router_kernel<<<T_TOKENS, 256>>>(x, gw, logits);
    scan_kernel<<<1, 1>>>();
    scatter_kernel<<<(T_TOKENS + 255) / 256, 256>>>();

    gemm1_mma<<<dim3(F_DIM / 64, MAX_RT), 256, G_SMEM>>>(x, w1, w3);
    gemm2_mma<<<dim3(H_DIM / 128, MAX_RT), 256, G_SMEM>>>(w2);

    combine_kernel<<<(T_TOKENS * (H_DIM / 4)) / 256, 256>>>(out);
}

// round 11
// speedup vs baseline: 2.3068x; 1.1334x over previous
#include <cuda_runtime.h>
#include <cstdint>
#include <math.h>

#define T_TOKENS 4096
#define H_DIM    2048
#define F_DIM    7168
#define N_EXP    8
#define NPAIRS   (T_TOKENS * 2)
#define BM       256
#define BK       32
#define MAX_RT   (NPAIRS / BM + N_EXP)   // 40

#define SROW     80                       // 32 bf16 = 64B + 16B pad, 16B-aligned
#define A_REG    (BM * SROW)              // 20480
#define B_REG    (128 * SROW)             // 10240
#define STAGE    (2 * A_REG + 2 * B_REG)  // 61440
#define G_SMEM   (3 * STAGE)              // 184320

#define W13_ELEMS ((size_t)N_EXP * F_DIM * H_DIM)

// ---------------- device scratch ----------------
__device__ __align__(16) unsigned short g_xh[(size_t)T_TOKENS * H_DIM];
__device__ __align__(16) unsigned short g_xl[(size_t)T_TOKENS * H_DIM];
__device__ __align__(16) unsigned short g_w1h[W13_ELEMS];
__device__ __align__(16) unsigned short g_w1l[W13_ELEMS];
__device__ __align__(16) unsigned short g_w3h[W13_ELEMS];
__device__ __align__(16) unsigned short g_w3l[W13_ELEMS];
__device__ __align__(16) unsigned short g_w2h[W13_ELEMS];
__device__ __align__(16) unsigned short g_w2l[W13_ELEMS];
__device__ __align__(16) unsigned short g_h_hi[(size_t)NPAIRS * F_DIM];
__device__ __align__(16) unsigned short g_h_lo[(size_t)NPAIRS * F_DIM];
__device__ __align__(16) float g_y[(size_t)NPAIRS * H_DIM];
__device__ int   g_gtoken[NPAIRS];
__device__ float g_gweight[NPAIRS];
__device__ int   g_pairrow[NPAIRS];
__device__ int   g_sel[NPAIRS];
__device__ float g_wt[NPAIRS];
__device__ int   g_counts[N_EXP];
__device__ int   g_cursor[N_EXP];
__device__ int   g_offsets[N_EXP + 1];
__device__ int   g_tile_e[MAX_RT];
__device__ int   g_tile_r[MAX_RT];
__device__ int   g_ntiles;

// ---------------- helpers ----------------
__device__ __forceinline__ uint32_t smem_u32(const void* p) {
    uint32_t a;
    asm("{ .reg .u64 t; cvta.to.shared.u64 t, %1; cvt.u32.u64 %0, t; }" : "=r"(a) : "l"(p));
    return a;
}
__device__ __forceinline__ uint32_t pkbf2(float lo, float hi) {
    uint32_t r;
    asm("cvt.rn.bf16x2.f32 %0, %1, %2;" : "=r"(r) : "f"(hi), "f"(lo));
    return r;
}
__device__ __forceinline__ void split4(float4 v, uint32_t& h0, uint32_t& h1,
                                       uint32_t& l0, uint32_t& l1) {
    h0 = pkbf2(v.x, v.y);
    h1 = pkbf2(v.z, v.w);
    float r0 = v.x - __uint_as_float(h0 << 16);
    float r1 = v.y - __uint_as_float(h0 & 0xffff0000u);
    float r2 = v.z - __uint_as_float(h1 << 16);
    float r3 = v.w - __uint_as_float(h1 & 0xffff0000u);
    l0 = pkbf2(r0, r1);
    l1 = pkbf2(r2, r3);
}
__device__ __forceinline__ void mma_bf16(float* d, const uint32_t* a, uint32_t b0, uint32_t b1) {
    asm volatile(
        "mma.sync.aligned.m16n8k16.row.col.f32.bf16.bf16.f32 "
        "{%0,%1,%2,%3}, {%4,%5,%6,%7}, {%8,%9}, {%0,%1,%2,%3};"
        : "+f"(d[0]), "+f"(d[1]), "+f"(d[2]), "+f"(d[3])
        : "r"(a[0]), "r"(a[1]), "r"(a[2]), "r"(a[3]), "r"(b0), "r"(b1));
}
#define LDM4(r0, r1, r2, r3, addr) \
    asm volatile("ldmatrix.sync.aligned.m8n8.x4.shared.b16 {%0,%1,%2,%3}, [%4];" \
                 : "=r"(r0), "=r"(r1), "=r"(r2), "=r"(r3) : "r"(addr))
#define CP16(dst, src) \
    asm volatile("cp.async.cg.shared.global [%0], [%1], 16;" :: "r"(dst), "l"(src) : "memory")
#define CP_COMMIT() asm volatile("cp.async.commit_group;" ::: "memory")
#define CP_WAIT1()  asm volatile("cp.async.wait_group 1;" ::: "memory")

// ---------------- precompute: fp32 -> bf16 hi/lo ----------------
__global__ void split_kernel(const float4* __restrict__ src, uint2* __restrict__ hi,
                             uint2* __restrict__ lo, long n4) {
    for (long i = (long)blockIdx.x * blockDim.x + threadIdx.x; i < n4;
         i += (long)gridDim.x * blockDim.x) {
        float4 v = src[i];
        uint32_t h0, h1, l0, l1;
        split4(v, h0, h1, l0, l1);
        hi[i] = make_uint2(h0, h1);
        lo[i] = make_uint2(l0, l1);
    }
}

// ---------------- routing ----------------
__global__ void init_kernel() {
    if (threadIdx.x < N_EXP) g_counts[threadIdx.x] = 0;
}

__global__ void router_kernel(const float* __restrict__ x, const float* __restrict__ gw,
                              float* __restrict__ logits_out) {
    const int t = blockIdx.x, tid = threadIdx.x;
    float acc[N_EXP];
#pragma unroll
    for (int e = 0; e < N_EXP; e++) acc[e] = 0.0f;
    const float4* xr = (const float4*)(x + (size_t)t * H_DIM);
    for (int i = tid; i < H_DIM / 4; i += 256) {
        float4 xv = xr[i];
#pragma unroll
        for (int e = 0; e < N_EXP; e++) {
            float4 gv = ((const float4*)(gw + (size_t)e * H_DIM))[i];
            acc[e] += xv.x * gv.x + xv.y * gv.y + xv.z * gv.z + xv.w * gv.w;
        }
    }
#pragma unroll
    for (int e = 0; e < N_EXP; e++)
#pragma unroll
        for (int off = 16; off > 0; off >>= 1)
            acc[e] += __shfl_down_sync(0xffffffffu, acc[e], off);
    __shared__ float sred[N_EXP][8];
    __shared__ float slog[N_EXP];
    const int w = tid >> 5, lane = tid & 31;
    if (lane == 0)
#pragma unroll
        for (int e = 0; e < N_EXP; e++) sred[e][w] = acc[e];
    __syncthreads();
    if (tid < N_EXP) {
        float s = 0.0f;
#pragma unroll
        for (int ww = 0; ww < 8; ww++) s += sred[tid][ww];
        slog[tid] = s;
        if (logits_out) logits_out[(size_t)t * N_EXP + tid] = s;
    }
    __syncthreads();
    if (tid == 0) {
        int i0 = 0; float v0 = slog[0];
#pragma unroll
        for (int e = 1; e < N_EXP; e++) if (slog[e] > v0) { v0 = slog[e]; i0 = e; }
        int i1 = -1; float v1 = -1e30f;
#pragma unroll
        for (int e = 0; e < N_EXP; e++) {
            if (e == i0) continue;
            if (slog[e] > v1) { v1 = slog[e]; i1 = e; }
        }
        float w0 = 1.0f / (1.0f + expf(v1 - v0));
        g_sel[2 * t] = i0; g_sel[2 * t + 1] = i1;
        g_wt[2 * t] = w0;  g_wt[2 * t + 1] = 1.0f - w0;
        atomicAdd(&g_counts[i0], 1);
        atomicAdd(&g_counts[i1], 1);
    }
}

__global__ void scan_kernel() {
    int off = 0, nt = 0;
    for (int e = 0; e < N_EXP; e++) {
        g_offsets[e] = off; g_cursor[e] = off;
        int c = g_counts[e];
        for (int i = 0; i < (c + BM - 1) / BM; i++) { g_tile_e[nt] = e; g_tile_r[nt] = i * BM; nt++; }
        off += c;
    }
    g_offsets[N_EXP] = off;
    g_ntiles = nt;
}

__global__ void scatter_kernel() {
    int t = blockIdx.x * blockDim.x + threadIdx.x;
    if (t >= T_TOKENS) return;
#pragma unroll
    for (int k = 0; k < 2; k++) {
        int e = g_sel[2 * t + k];
        int idx = atomicAdd(&g_cursor[e], 1);
        g_gtoken[idx] = t;
        g_gweight[idx] = g_wt[2 * t + k];
        g_pairrow[2 * t + k] = idx;
    }
}

// ======================= GEMM1: 256x128 CTA, cp.async + ldmatrix ===========
// blockIdx.x = row tile, blockIdx.y = f tile (64 w1-rows + 64 w3-rows)
__global__ void __launch_bounds__(256, 1)
gemm1_mma() {
    const int rt = blockIdx.x;
    if (rt >= g_ntiles) return;
    const int e = g_tile_e[rt];
    const int row_base = g_offsets[e] + g_tile_r[rt];
    const int n_valid  = g_offsets[e + 1] - row_base;
    const int f0 = blockIdx.y * 64;
    const int t  = threadIdx.x;
    const int wid = t >> 5, lane = t & 31;
    const int wm = wid & 3, wn = wid >> 2;
    const int g = lane >> 2, cc = lane & 3;

    extern __shared__ __align__(16) char smem[];
    const uint32_t sb = smem_u32(smem);

    // producers
    const int ar = t >> 2, aseg = t & 3;
    const unsigned short* aH[4];
    const unsigned short* aL[4];
    uint32_t aOff[4];
#pragma unroll
    for (int j = 0; j < 4; j++) {
        int row = ar + j * 64;
        int tok = g_gtoken[min(row_base + row, NPAIRS - 1)];
        aH[j] = g_xh + (size_t)tok * H_DIM + aseg * 8;
        aL[j] = g_xl + (size_t)tok * H_DIM + aseg * 8;
        aOff[j] = (uint32_t)row * SROW + aseg * 16;
    }
    const int br = t >> 1, bq = (t & 1) * 2;
    size_t brow = (size_t)e * F_DIM + f0 + (br < 64 ? br : br - 64);
    const unsigned short* bH = (br < 64 ? g_w1h : g_w3h) + brow * H_DIM;
    const unsigned short* bL = (br < 64 ? g_w1l : g_w3l) + brow * H_DIM;
    const uint32_t bOff = (uint32_t)br * SROW + bq * 16;

    auto issue = [&](int s, int c) {
        uint32_t st = sb + s * STAGE;
#pragma unroll
        for (int j = 0; j < 4; j++) {
            CP16(st + aOff[j],         aH[j] + c * BK);
            CP16(st + A_REG + aOff[j], aL[j] + c * BK);
        }
#pragma unroll
        for (int q = 0; q < 2; q++) {
            CP16(st + 2 * A_REG + bOff + q * 16,         bH + c * BK + (bq + q) * 8);
            CP16(st + 2 * A_REG + B_REG + bOff + q * 16, bL + c * BK + (bq + q) * 8);
        }
    };

    float acc[4][8][4];
#pragma unroll
    for (int mt = 0; mt < 4; mt++)
#pragma unroll
        for (int nt = 0; nt < 8; nt++)
#pragma unroll
            for (int i = 0; i < 4; i++) acc[mt][nt][i] = 0.0f;

    const uint32_t aLane = (uint32_t)(lane & 15) * SROW + (lane >> 4) * 16;
    const uint32_t bLane = (uint32_t)(((lane & 16) >> 1) + (lane & 7)) * SROW + ((lane >> 3) & 1) * 16;

    issue(0, 0); CP_COMMIT();
    issue(1, 1); CP_COMMIT();

    const int NC = H_DIM / BK;
    for (int c = 0; c < NC; c++) {
        CP_WAIT1();
        __syncthreads();
        if (c + 2 < NC) issue((c + 2) % 3, c + 2);
        CP_COMMIT();

        const uint32_t stb = sb + (c % 3) * STAGE;
        const uint32_t AhB = stb, AlB = stb + A_REG;
        const uint32_t BhB = stb + 2 * A_REG, BlB = BhB + B_REG;
#pragma unroll
        for (int ks = 0; ks < 2; ks++) {
            uint32_t ah[4][4], al[4][4];
#pragma unroll
            for (int mt = 0; mt < 4; mt++) {
                uint32_t ao = (uint32_t)(wm * 64 + mt * 16) * SROW + ks * 32 + aLane;
                LDM4(ah[mt][0], ah[mt][1], ah[mt][2], ah[mt][3], AhB + ao);
                LDM4(al[mt][0], al[mt][1], al[mt][2], al[mt][3], AlB + ao);
            }
#pragma unroll
            for (int p = 0; p < 4; p++) {
                uint32_t bo = (uint32_t)(wn * 64 + p * 16) * SROW + ks * 32 + bLane;
                uint32_t bh0, bh1, bh2, bh3, bl0, bl1, bl2, bl3;
                LDM4(bh0, bh1, bh2, bh3, BhB + bo);
                LDM4(bl0, bl1, bl2, bl3, BlB + bo);
#pragma unroll
                for (int mt = 0; mt < 4; mt++) {
                    mma_bf16(acc[mt][2 * p],     ah[mt], bh0, bh1);
                    mma_bf16(acc[mt][2 * p],     ah[mt], bl0, bl1);
                    mma_bf16(acc[mt][2 * p],     al[mt], bh0, bh1);
                    mma_bf16(acc[mt][2 * p + 1], ah[mt], bh2, bh3);
                    mma_bf16(acc[mt][2 * p + 1], ah[mt], bl2, bl3);
                    mma_bf16(acc[mt][2 * p + 1], al[mt], bh2, bh3);
                }
            }
        }
    }
    __syncthreads();

    // epilogue: exchange w3 result, SwiGLU, split to bf16 hi/lo
    float* h3buf = (float*)smem;   // [256][68]
    if (wn == 1) {
#pragma unroll
        for (int mt = 0; mt < 4; mt++)
#pragma unroll
            for (int nt = 0; nt < 8; nt++) {
                int m0 = wm * 64 + mt * 16 + g;
                int f  = nt * 8 + 2 * cc;
                *(float2*)&h3buf[m0 * 68 + f]       = make_float2(acc[mt][nt][0], acc[mt][nt][1]);
                *(float2*)&h3buf[(m0 + 8) * 68 + f] = make_float2(acc[mt][nt][2], acc[mt][nt][3]);
            }
    }
    __syncthreads();
    if (wn == 0) {
#pragma unroll
        for (int mt = 0; mt < 4; mt++)
#pragma unroll
            for (int nt = 0; nt < 8; nt++)
#pragma unroll
                for (int hf = 0; hf < 2; hf++) {
                    int m = wm * 64 + mt * 16 + g + hf * 8;
                    if (m >= n_valid) continue;
                    int f = nt * 8 + 2 * cc;
                    float s1a = acc[mt][nt][hf * 2], s1b = acc[mt][nt][hf * 2 + 1];
                    float2 h3 = *(const float2*)&h3buf[m * 68 + f];
                    float ha = s1a / (1.0f + __expf(-s1a)) * h3.x;
                    float hb = s1b / (1.0f + __expf(-s1b)) * h3.y;
                    uint32_t hh = pkbf2(ha, hb);
                    uint32_t ll = pkbf2(ha - __uint_as_float(hh << 16),
                                        hb - __uint_as_float(hh & 0xffff0000u));
                    size_t go = (size_t)(row_base + m) * F_DIM + f0 + f;
                    *(uint32_t*)(g_h_hi + go) = hh;
                    *(uint32_t*)(g_h_lo + go) = ll;
                }
    }
}

// ======================= GEMM2: 256x128 CTA ================================
// blockIdx.x = h tile (128 cols), blockIdx.y = row tile
__global__ void __launch_bounds__(256, 1)
gemm2_mma() {
    const int rt = blockIdx.y;
    if (rt >= g_ntiles) return;
    const int e = g_tile_e[rt];
    const int row_base = g_offsets[e] + g_tile_r[rt];
    const int n_valid  = g_offsets[e + 1] - row_base;
    const int h0 = blockIdx.x * 128;
    const int t  = threadIdx.x;
    const int wid = t >> 5, lane = t & 31;
    const int wm = wid & 3, wn = wid >> 2;
    const int g = lane >> 2, cc = lane & 3;

    extern __shared__ __align__(16) char smem[];
    const uint32_t sb = smem_u32(smem);

    const int ar = t >> 2, aseg = t & 3;
    const unsigned short* aH[4];
    const unsigned short* aL[4];
    uint32_t aOff[4];
#pragma unroll
    for (int j = 0; j < 4; j++) {
        int row = ar + j * 64;
        int grow = min(row_base + row, NPAIRS - 1);
        aH[j] = g_h_hi + (size_t)grow * F_DIM + aseg * 8;
        aL[j] = g_h_lo + (size_t)grow * F_DIM + aseg * 8;
        aOff[j] = (uint32_t)row * SROW + aseg * 16;
    }
    const int br = t >> 1, bq = (t & 1) * 2;
    size_t brow = (size_t)e * H_DIM + h0 + br;
    const unsigned short* bH = g_w2h + brow * F_DIM;
    const unsigned short* bL = g_w2l + brow * F_DIM;
    const uint32_t bOff = (uint32_t)br * SROW + bq * 16;

    auto issue = [&](int s, int c) {
        uint32_t st = sb + s * STAGE;
#pragma unroll
        for (int j = 0; j < 4; j++) {
            CP16(st + aOff[j],         aH[j] + c * BK);
            CP16(st + A_REG + aOff[j], aL[j] + c * BK);
        }
#pragma unroll
        for (int q = 0; q < 2; q++) {
            CP16(st + 2 * A_REG + bOff + q * 16,         bH + c * BK + (bq + q) * 8);
            CP16(st + 2 * A_REG + B_REG + bOff + q * 16, bL + c * BK + (bq + q) * 8);
        }
    };

    float acc[4][8][4];
#pragma unroll
    for (int mt = 0; mt < 4; mt++)
#pragma unroll
        for (int nt = 0; nt < 8; nt++)
#pragma unroll
            for (int i = 0; i < 4; i++) acc[mt][nt][i] = 0.0f;

    const uint32_t aLane = (uint32_t)(lane & 15) * SROW + (lane >> 4) * 16;
    const uint32_t bLane = (uint32_t)(((lane & 16) >> 1) + (lane & 7)) * SROW + ((lane >> 3) & 1) * 16;

    issue(0, 0); CP_COMMIT();
    issue(1, 1); CP_COMMIT();

    const int NC = F_DIM / BK;
    for (int c = 0; c < NC; c++) {
        CP_WAIT1();
        __syncthreads();
        if (c + 2 < NC) issue((c + 2) % 3, c + 2);
        CP_COMMIT();

        const uint32_t stb = sb + (c % 3) * STAGE;
        const uint32_t AhB = stb, AlB = stb + A_REG;
        const uint32_t BhB = stb + 2 * A_REG, BlB = BhB + B_REG;
#pragma unroll
        for (int ks = 0; ks < 2; ks++) {
            uint32_t ah[4][4], al[4][4];
#pragma unroll
            for (int mt = 0; mt < 4; mt++) {
                uint32_t ao = (uint32_t)(wm * 64 + mt * 16) * SROW + ks * 32 + aLane;
                LDM4(ah[mt][0], ah[mt][1], ah[mt][2], ah[mt][3], AhB + ao);
                LDM4(al[mt][0], al[mt][1], al[mt][2], al[mt][3], AlB + ao);
            }
#pragma unroll
            for (int p = 0; p < 4; p++) {
                uint32_t bo = (uint32_t)(wn * 64 + p * 16) * SROW + ks * 32 + bLane;
                uint32_t bh0, bh1, bh2, bh3, bl0, bl1, bl2, bl3;
                LDM4(bh0, bh1, bh2, bh3, BhB + bo);
                LDM4(bl0, bl1, bl2, bl3, BlB + bo);
#pragma unroll
                for (int mt = 0; mt < 4; mt++) {
                    mma_bf16(acc[mt][2 * p],     ah[mt], bh0, bh1);
                    mma_bf16(acc[mt][2 * p],     ah[mt], bl0, bl1);
                    mma_bf16(acc[mt][2 * p],     al[mt], bh0, bh1);
                    mma_bf16(acc[mt][2 * p + 1], ah[mt], bh2, bh3);
                    mma_bf16(acc[mt][2 * p + 1], ah[mt], bl2, bl3);
                    mma_bf16(acc[mt][2 * p + 1], al[mt], bh2, bh3);
                }
            }
        }
    }

    // epilogue: scale by routing weight, write fp32 y
#pragma unroll
    for (int mt = 0; mt < 4; mt++)
#pragma unroll
        for (int hf = 0; hf < 2; hf++) {
            int m = wm * 64 + mt * 16 + g + hf * 8;
            if (m >= n_valid) continue;
            float wgt = g_gweight[row_base + m];
            float* yrow = g_y + (size_t)(row_base + m) * H_DIM + h0 + wn * 64;
#pragma unroll
            for (int nt = 0; nt < 8; nt++) {
                *(float2*)&yrow[nt * 8 + 2 * cc] =
                    make_float2(acc[mt][nt][hf * 2] * wgt, acc[mt][nt][hf * 2 + 1] * wgt);
            }
        }
}

// ---------------- combine ----------------
__global__ void combine_kernel(float* __restrict__ out) {
    int idx = blockIdx.x * blockDim.x + threadIdx.x;
    int t = idx / (H_DIM / 4), c = idx % (H_DIM / 4);
    int p0 = g_pairrow[2 * t], p1 = g_pairrow[2 * t + 1];
    float4 y0 = *(const float4*)&g_y[(size_t)p0 * H_DIM + c * 4];
    float4 y1 = *(const float4*)&g_y[(size_t)p1 * H_DIM + c * 4];
    ((float4*)out)[idx] = make_float4(y0.x + y1.x, y0.y + y1.y, y0.z + y1.z, y0.w + y1.w);
}

// ---------------------------------------------------------------------------
extern "C" void kernel_launch(void* const* d_in, const int* in_sizes, int n_in,
                              void* d_out, int out_size) {
    const float* x  = (const float*)d_in[0];
    const float* gw = (const float*)d_in[1];
    const float* w1 = (const float*)d_in[2];
    const float* w2 = (const float*)d_in[3];
    const float* w3 = (const float*)d_in[4];
    float* out = (float*)d_out;
    float* logits = nullptr;
    if (out_size >= T_TOKENS * H_DIM + T_TOKENS * N_EXP)
        logits = out + (size_t)T_TOKENS * H_DIM;

    cudaFuncSetAttribute(gemm1_mma, cudaFuncAttributeMaxDynamicSharedMemorySize, G_SMEM);
    cudaFuncSetAttribute(gemm2_mma, cudaFuncAttributeMaxDynamicSharedMemorySize, G_SMEM);

    unsigned short* xh; cudaGetSymbolAddress((void**)&xh, g_xh);
    unsigned short* xl; cudaGetSymbolAddress((void**)&xl, g_xl);
    unsigned short* w1h; cudaGetSymbolAddress((void**)&w1h, g_w1h);
    unsigned short* w1l; cudaGetSymbolAddress((void**)&w1l, g_w1l);
    unsigned short* w3h; cudaGetSymbolAddress((void**)&w3h, g_w3h);
    unsigned short* w3l; cudaGetSymbolAddress((void**)&w3l, g_w3l);
    unsigned short* w2h; cudaGetSymbolAddress((void**)&w2h, g_w2h);
    unsigned short* w2l; cudaGetSymbolAddress((void**)&w2l, g_w2l);

    init_kernel<<<1, 32>>>();
    router_kernel<<<T_TOKENS, 256>>>(x, gw, logits);
    scan_kernel<<<1, 1>>>();
    scatter_kernel<<<(T_TOKENS + 255) / 256, 256>>>();

    split_kernel<<<4096, 256>>>((const float4*)x, (uint2*)xh, (uint2*)xl,
                                (long)T_TOKENS * H_DIM / 4);
    split_kernel<<<16384, 256>>>((const float4*)w1, (uint2*)w1h, (uint2*)w1l,
                                 (long)(W13_ELEMS / 4));
    split_kernel<<<16384, 256>>>((const float4*)w3, (uint2*)w3h, (uint2*)w3l,
                                 (long)(W13_ELEMS / 4));
    split_kernel<<<16384, 256>>>((const float4*)w2, (uint2*)w2h, (uint2*)w2l,
                                 (long)(W13_ELEMS / 4));

    gemm1_mma<<<dim3(MAX_RT, F_DIM / 64), 256, G_SMEM>>>();
    gemm2_mma<<<dim3(H_DIM / 128, MAX_RT), 256, G_SMEM>>>();

    combine_kernel<<<(T_TOKENS * (H_DIM / 4)) / 256, 256>>>(out);
}